// round 1
// baseline (speedup 1.0000x reference)
#include <cuda_runtime.h>
#include <cstdint>

#define M_DIM 8192
#define K_DIM 4096
#define N_DIM 16384

// Scratch: device globals (allocation-free rule)
static __device__ __align__(16) signed char g_qx[(size_t)M_DIM * K_DIM];   // 32 MB
static __device__ __align__(16) signed char g_wq[(size_t)N_DIM * K_DIM];   // 64 MB
static __device__ float g_sx[M_DIM];

// ---------------------------------------------------------------------------
// Kernel 1: per-row absmax + symmetric int8 quantization of activations.
// One block (256 threads) per row; K=4096 -> 16 floats/thread.
// Matches reference bit-path: scale = absmax/127 (true div),
// q = rint(x/scale) (round half to even, like jnp.round).
// ---------------------------------------------------------------------------
__global__ void quant_rows_kernel(const float* __restrict__ x) {
    int row = blockIdx.x;
    int t = threadIdx.x;
    const float4* xr = reinterpret_cast<const float4*>(x + (size_t)row * K_DIM);
    float4 v[4];
    float amax = 0.0f;
#pragma unroll
    for (int i = 0; i < 4; i++) {
        v[i] = xr[t + i * 256];
        amax = fmaxf(amax, fabsf(v[i].x));
        amax = fmaxf(amax, fabsf(v[i].y));
        amax = fmaxf(amax, fabsf(v[i].z));
        amax = fmaxf(amax, fabsf(v[i].w));
    }
    __shared__ float red[8];
    __shared__ float s_scale;
#pragma unroll
    for (int o = 16; o > 0; o >>= 1)
        amax = fmaxf(amax, __shfl_xor_sync(0xffffffffu, amax, o));
    if ((t & 31) == 0) red[t >> 5] = amax;
    __syncthreads();
    if (t == 0) {
        float m = red[0];
#pragma unroll
        for (int i = 1; i < 8; i++) m = fmaxf(m, red[i]);
        float sc = m / 127.0f;     // exact IEEE division, matches reference
        s_scale = sc;
        g_sx[row] = sc;
    }
    __syncthreads();
    float scale = s_scale;
    char4* qr = reinterpret_cast<char4*>(g_qx + (size_t)row * K_DIM);
#pragma unroll
    for (int i = 0; i < 4; i++) {
        char4 q;
        q.x = (signed char)__float2int_rn(v[i].x / scale);
        q.y = (signed char)__float2int_rn(v[i].y / scale);
        q.z = (signed char)__float2int_rn(v[i].z / scale);
        q.w = (signed char)__float2int_rn(v[i].w / scale);
        qr[t + i * 256] = q;
    }
}

// ---------------------------------------------------------------------------
// Kernel 2: repack int32 weights (values in [-127,127]) into int8.
// ---------------------------------------------------------------------------
__global__ void convert_w_kernel(const int4* __restrict__ w) {
    int idx = blockIdx.x * blockDim.x + threadIdx.x;   // over N*K/4 = 16777216
    int4 v = w[idx];
    char4 q;
    q.x = (signed char)v.x;
    q.y = (signed char)v.y;
    q.z = (signed char)v.z;
    q.w = (signed char)v.w;
    reinterpret_cast<char4*>(g_wq)[idx] = q;
}

// ---------------------------------------------------------------------------
// Kernel 3: int8 GEMM with int32 accumulation via mma.sync.m16n8k32.s8,
// fused dequant epilogue: out = acc * sx[m] * ws[n] + bias[n].
// A = g_qx [M,K] row-major (k contiguous) -> mma "row"
// B = g_wq [N,K] row-major (k contiguous) -> mma "col"
// ---------------------------------------------------------------------------
#define BM 128
#define BN 128
#define BK 64
#define SROW 80                   // padded smem row stride (bytes): conflict-free frag LDS
#define NKITER (K_DIM / BK)       // 64

__device__ __forceinline__ void cp16(uint32_t s, const void* g) {
    asm volatile("cp.async.cg.shared.global [%0], [%1], 16;\n" :: "r"(s), "l"(g));
}

__global__ __launch_bounds__(256, 1) void gemm_s8_kernel(const float* __restrict__ wscale,
                                                         const float* __restrict__ bias,
                                                         float* __restrict__ out) {
    __shared__ signed char sA[2][BM * SROW];
    __shared__ signed char sB[2][BN * SROW];

    // tile decode with L2 group swizzle (8 m-tiles per group)
    const int tiles_n = N_DIM / BN;          // 128
    const int GM = 8;
    int gid = blockIdx.x;
    int per_group = GM * tiles_n;            // 1024
    int group = gid / per_group;
    int rem = gid - group * per_group;
    int tm = group * GM + (rem & (GM - 1));  // tiles_m=64 divisible by GM
    int tn = rem >> 3;

    const int t = threadIdx.x;
    const int wid = t >> 5;
    const int lane = t & 31;
    const int warpM = wid & 1;               // 2 warps along M
    const int warpN = wid >> 1;              // 4 warps along N
    const int gID = lane >> 2;
    const int tig = lane & 3;

    const signed char* gA = g_qx + (size_t)(tm * BM) * K_DIM;
    const signed char* gB = g_wq + (size_t)(tn * BN) * K_DIM;

    const int ldrow = t >> 2;                // 0..63
    const int ldcol = (t & 3) * 16;          // 0,16,32,48

    uint32_t sAb[2], sBb[2];
    sAb[0] = (uint32_t)__cvta_generic_to_shared(&sA[0][0]);
    sAb[1] = (uint32_t)__cvta_generic_to_shared(&sA[1][0]);
    sBb[0] = (uint32_t)__cvta_generic_to_shared(&sB[0][0]);
    sBb[1] = (uint32_t)__cvta_generic_to_shared(&sB[1][0]);

    auto load_stage = [&](int buf, int kt) {
        int koff = kt * BK + ldcol;
        cp16(sAb[buf] + ldrow * SROW + ldcol,        gA + (size_t)ldrow * K_DIM + koff);
        cp16(sAb[buf] + (ldrow + 64) * SROW + ldcol, gA + (size_t)(ldrow + 64) * K_DIM + koff);
        cp16(sBb[buf] + ldrow * SROW + ldcol,        gB + (size_t)ldrow * K_DIM + koff);
        cp16(sBb[buf] + (ldrow + 64) * SROW + ldcol, gB + (size_t)(ldrow + 64) * K_DIM + koff);
        asm volatile("cp.async.commit_group;\n");
    };

    int acc[4][4][4];
#pragma unroll
    for (int mf = 0; mf < 4; mf++)
#pragma unroll
        for (int nf = 0; nf < 4; nf++)
#pragma unroll
            for (int i = 0; i < 4; i++) acc[mf][nf][i] = 0;

    load_stage(0, 0);

    for (int kt = 0; kt < NKITER; kt++) {
        int buf = kt & 1;
        if (kt + 1 < NKITER) {
            load_stage(buf ^ 1, kt + 1);
            asm volatile("cp.async.wait_group 1;\n");
        } else {
            asm volatile("cp.async.wait_group 0;\n");
        }
        __syncthreads();

#pragma unroll
        for (int ks = 0; ks < 2; ks++) {
            const int col = ks * 32 + tig * 4;
            uint32_t a[4][4], b[4][2];
#pragma unroll
            for (int mf = 0; mf < 4; mf++) {
                int r0 = warpM * 64 + mf * 16 + gID;
                const signed char* p = &sA[buf][r0 * SROW + col];
                a[mf][0] = *(const uint32_t*)(p);
                a[mf][1] = *(const uint32_t*)(p + 8 * SROW);
                a[mf][2] = *(const uint32_t*)(p + 16);
                a[mf][3] = *(const uint32_t*)(p + 8 * SROW + 16);
            }
#pragma unroll
            for (int nf = 0; nf < 4; nf++) {
                int c0 = warpN * 32 + nf * 8 + gID;
                const signed char* p = &sB[buf][c0 * SROW + col];
                b[nf][0] = *(const uint32_t*)(p);
                b[nf][1] = *(const uint32_t*)(p + 16);
            }
#pragma unroll
            for (int mf = 0; mf < 4; mf++)
#pragma unroll
                for (int nf = 0; nf < 4; nf++)
                    asm volatile(
                        "mma.sync.aligned.m16n8k32.row.col.s32.s8.s8.s32 "
                        "{%0,%1,%2,%3}, {%4,%5,%6,%7}, {%8,%9}, {%0,%1,%2,%3};\n"
                        : "+r"(acc[mf][nf][0]), "+r"(acc[mf][nf][1]),
                          "+r"(acc[mf][nf][2]), "+r"(acc[mf][nf][3])
                        : "r"(a[mf][0]), "r"(a[mf][1]), "r"(a[mf][2]), "r"(a[mf][3]),
                          "r"(b[nf][0]), "r"(b[nf][1]));
        }
        __syncthreads();
    }

    // epilogue: dequant + bias, direct to gmem (32B sectors per row-segment)
#pragma unroll
    for (int mf = 0; mf < 4; mf++) {
        int r0 = tm * BM + warpM * 64 + mf * 16 + gID;
        float sx0 = g_sx[r0];
        float sx1 = g_sx[r0 + 8];
        float* o0 = out + (size_t)r0 * N_DIM;
        float* o1 = out + (size_t)(r0 + 8) * N_DIM;
#pragma unroll
        for (int nf = 0; nf < 4; nf++) {
            int c = tn * BN + warpN * 32 + nf * 8 + tig * 2;
            float w0 = wscale[c], w1 = wscale[c + 1];
            float b0 = bias[c], b1 = bias[c + 1];
            o0[c]     = (float)acc[mf][nf][0] * sx0 * w0 + b0;
            o0[c + 1] = (float)acc[mf][nf][1] * sx0 * w1 + b1;
            o1[c]     = (float)acc[mf][nf][2] * sx1 * w0 + b0;
            o1[c + 1] = (float)acc[mf][nf][3] * sx1 * w1 + b1;
        }
    }
}

// ---------------------------------------------------------------------------
extern "C" void kernel_launch(void* const* d_in, const int* in_sizes, int n_in,
                              void* d_out, int out_size) {
    (void)in_sizes; (void)n_in; (void)out_size;
    const float* x      = (const float*)d_in[0];
    const int*   wq     = (const int*)d_in[1];
    const float* wscale = (const float*)d_in[2];
    const float* bias   = (const float*)d_in[3];
    float* out = (float*)d_out;

    quant_rows_kernel<<<M_DIM, 256>>>(x);

    int conv_blocks = (N_DIM / 4) * (K_DIM / 256);   // 16777216 / 256 = 65536
    convert_w_kernel<<<conv_blocks, 256>>>((const int4*)wq);

    int gemm_blocks = (M_DIM / BM) * (N_DIM / BN);   // 64 * 128 = 8192
    gemm_s8_kernel<<<gemm_blocks, 256>>>(wscale, bias, out);
}